// round 7
// baseline (speedup 1.0000x reference)
#include <cuda_runtime.h>
#include <math.h>

#define BATCH 8
#define NVERT 8192
#define NPD 64
#define NSAMP (NPD*NPD)      // 4096
#define NBLK 64              // blocks per batch
#define NCHUNK 128           // chunk-units per batch (2 per block)
#define JBLOCK (NVERT/NBLK)  // 128 vertices per block
#define JHALF (JBLOCK/2)     // 64 vertices per half (warp pair)
#define JT 16                // j's per stage (double-buffered)
#define NSTAGE (JHALF/JT)    // 4
#define NTHR 128

// ---- device scratch (no allocations allowed) ----
__device__ float4   g_stats[BATCH*NBLK];
__device__ float    g_partial[BATCH*NCHUNK*NSAMP];  // 16 MB partials
__device__ float    g_K[BATCH*NSAMP];
__device__ float    g_ssum[BATCH*NBLK];
__device__ unsigned g_cntA[BATCH];
__device__ unsigned g_cntB[BATCH];
__device__ unsigned g_cntC[BATCH];

__device__ __forceinline__ float ex2f(float x) {
    float y; asm("ex2.approx.ftz.f32 %0, %1;" : "=f"(y) : "f"(x)); return y;
}
// Packed 2xFP32 FMA (Blackwell FFMA2, PTX-only)
__device__ __forceinline__ unsigned long long ffma2(
    unsigned long long a, unsigned long long b, unsigned long long c)
{
    unsigned long long d;
    asm("fma.rn.f32x2 %0, %1, %2, %3;" : "=l"(d) : "l"(a), "l"(b), "l"(c));
    return d;
}
__device__ __forceinline__ void spin_until(volatile unsigned* p, unsigned v) {
    while (*p < v) { }
}

// ==================== single fused persistent kernel ====================
// grid = 512 blocks (batch = blk>>6, chunk = blk&63), 128 threads.
// Split-K inside the block: warps 0-1 = half 0 (j 0..63), warps 2-3 = half 1.
// Each half computes a full 64x64 partial with 8x8 per-thread tiles.
__global__ void __launch_bounds__(NTHR, 4) k_fused(const float* __restrict__ T,
                                                   const float* __restrict__ S,
                                                   float* __restrict__ out)
{
    __shared__ __align__(16) float2 sExd[2][2][JT][NPD];  // [half][buf], dup (ex,ex): 16 KB
    __shared__ __align__(16) float  sEy[2][2][JT][NPD];   // 8 KB
    __shared__ __align__(16) float2 sT[JBLOCK];           // 1 KB
    __shared__ __align__(16) float4 s4[NTHR];             // 2 KB
    __shared__ float  sG[NPD];
    __shared__ float4 sW[4];
    __shared__ float  sKx, sCoeff, sInv;
    __shared__ int    sIsLast;

    const int tid  = threadIdx.x;
    const int bb   = blockIdx.x >> 6;
    const int ch   = blockIdx.x & 63;
    const int half = tid >> 6;        // 0/1 -> warp pair
    const int ht   = tid & 63;        // thread within half

    // ---- stage T chunk + grid ----
    ((float2*)sT)[tid] = ((const float2*)(T + (bb * NVERT + ch * JBLOCK) * 2))[tid];
    if (tid < NPD) sG[tid] = S[tid * 2 + 1];   // S[0,c,1] = g[c] exactly
    __syncthreads();

    // ================= Phase A: chunk stats + sigma =================
    {
        float2 v0 = sT[tid];                   // one vertex per thread
        float sx = v0.x, sy = v0.y;
        float sxx = v0.x * v0.x, syy = v0.y * v0.y;
        #pragma unroll
        for (int o = 16; o; o >>= 1) {
            sx  += __shfl_xor_sync(~0u, sx,  o);
            sxx += __shfl_xor_sync(~0u, sxx, o);
            sy  += __shfl_xor_sync(~0u, sy,  o);
            syy += __shfl_xor_sync(~0u, syy, o);
        }
        if ((tid & 31) == 0) sW[tid >> 5] = make_float4(sx, sxx, sy, syy);
        __syncthreads();
        if (tid == 0) {
            float4 r = sW[0];
            #pragma unroll
            for (int w = 1; w < 4; ++w) {
                r.x += sW[w].x; r.y += sW[w].y; r.z += sW[w].z; r.w += sW[w].w;
            }
            g_stats[blockIdx.x] = r;
            __threadfence();
            atomicAdd(&g_cntA[bb], 1u);
            spin_until(&g_cntA[bb], NBLK);
            __threadfence();
        }
        __syncthreads();
    }
    if (tid < 32) {
        float4 sa = __ldcg(&g_stats[bb * NBLK + tid]);
        float4 sb = __ldcg(&g_stats[bb * NBLK + 32 + tid]);
        float sx = sa.x + sb.x, sxx = sa.y + sb.y;
        float sy = sa.z + sb.z, syy = sa.w + sb.w;
        #pragma unroll
        for (int o = 16; o; o >>= 1) {
            sx  += __shfl_xor_sync(~0u, sx,  o);
            sxx += __shfl_xor_sync(~0u, sxx, o);
            sy  += __shfl_xor_sync(~0u, sy,  o);
            syy += __shfl_xor_sync(~0u, syy, o);
        }
        if (tid == 0) {
            const double n = (double)NVERT;
            double vx = ((double)sxx - (double)sx*(double)sx/n) / (n - 1.0);
            double vy = ((double)syy - (double)sy*(double)sy/n) / (n - 1.0);
            if (vx < 0.0) vx = 0.0;
            if (vy < 0.0) vy = 0.0;
            double sigma = 0.5 * (sqrt(vx) + sqrt(vy));
            const double bd = 1.0 / 63.0;
            if (sigma < bd) sigma = bd;
            const double p  = exp2(13.0 / 3.0);   // CN=-p/2, CF=p/(2pi)
            const double s2 = sigma * sigma;
            sKx    = (float)((-0.5 * p) / s2 * 1.4426950408889634);
            sCoeff = (float)((p / (2.0 * M_PI)) / s2 / (double)NVERT);
        }
    }
    __syncthreads();
    const float kx = sKx;

    // ================= Phase B: split-K GEMM, 8x8 per-thread tiles =================
    unsigned long long acc[8][4];
    #pragma unroll
    for (int i = 0; i < 8; ++i)
        #pragma unroll
        for (int c = 0; c < 4; ++c) acc[i][c] = 0ull;

    const int ta = ht >> 3;          // 0..7 -> a rows [ta*8, +8)
    const int tb = ht & 7;           // 0..7 -> b cols [tb*8, +8)
    const float ga = sG[ht];         // fill: one grid point per thread
    const int jb0 = half * JHALF;

    // Prologue: fill stage 0 into buffer 0 (each thread: 16 j's at its grid point)
    #pragma unroll
    for (int jj = 0; jj < JT; ++jj) {
        float2 tv = sT[jb0 + jj];
        float dx = ga - tv.x, dy = ga - tv.y;
        float ex = ex2f(kx * (dx * dx));
        float ey = ex2f(kx * (dy * dy));
        sExd[half][0][jj][ht] = make_float2(ex, ex);
        sEy[half][0][jj][ht]  = ey;
    }
    __syncthreads();

    for (int s = 0; s < NSTAGE; ++s) {
        const int cur = s & 1;
        if (s + 1 < NSTAGE) {
            const int nxt = cur ^ 1;
            #pragma unroll
            for (int jj = 0; jj < JT; ++jj) {
                float2 tv = sT[jb0 + (s + 1) * JT + jj];
                float dx = ga - tv.x, dy = ga - tv.y;
                float ex = ex2f(kx * (dx * dx));
                float ey = ex2f(kx * (dy * dy));
                sExd[half][nxt][jj][ht] = make_float2(ex, ex);
                sEy[half][nxt][jj][ht]  = ey;
            }
        }
        #pragma unroll
        for (int jj = 0; jj < JT; ++jj) {
            const ulonglong2* axp = (const ulonglong2*)&sExd[half][cur][jj][ta * 8];
            const ulonglong2* bp  = (const ulonglong2*)&sEy[half][cur][jj][tb * 8];
            ulonglong2 b01 = bp[0];          // (b0,b1),(b2,b3)
            ulonglong2 b23 = bp[1];          // (b4,b5),(b6,b7)
            #pragma unroll
            for (int i = 0; i < 4; ++i) {
                ulonglong2 ax = axp[i];      // (a2i,a2i),(a2i+1,a2i+1)
                acc[2*i  ][0] = ffma2(ax.x, b01.x, acc[2*i  ][0]);
                acc[2*i  ][1] = ffma2(ax.x, b01.y, acc[2*i  ][1]);
                acc[2*i  ][2] = ffma2(ax.x, b23.x, acc[2*i  ][2]);
                acc[2*i  ][3] = ffma2(ax.x, b23.y, acc[2*i  ][3]);
                acc[2*i+1][0] = ffma2(ax.y, b01.x, acc[2*i+1][0]);
                acc[2*i+1][1] = ffma2(ax.y, b01.y, acc[2*i+1][1]);
                acc[2*i+1][2] = ffma2(ax.y, b23.x, acc[2*i+1][2]);
                acc[2*i+1][3] = ffma2(ax.y, b23.y, acc[2*i+1][3]);
            }
        }
        __syncthreads();
    }

    // write this half's 64x64 partial (chunk-unit cu = ch*2 + half)
    {
        float* outp = g_partial + ((size_t)(bb * NCHUNK + ch * 2 + half)) * NSAMP;
        #pragma unroll
        for (int i = 0; i < 8; ++i) {
            ulonglong2 v0; v0.x = acc[i][0]; v0.y = acc[i][1];
            ulonglong2 v1; v1.x = acc[i][2]; v1.y = acc[i][3];
            float* rp = outp + (ta * 8 + i) * NPD + tb * 8;
            *(ulonglong2*)rp       = v0;
            *(ulonglong2*)(rp + 4) = v1;
        }
    }
    __threadfence();
    __syncthreads();
    if (tid == 0) {
        atomicAdd(&g_cntB[bb], 1u);
        spin_until(&g_cntB[bb], NBLK);
        __threadfence();
    }
    __syncthreads();

    // ================= Phase C: cooperative reduce + segment sums =================
    // Block (bb,ch) reduces image float4 positions [ch*16, ch*16+16) over 128 chunk-units.
    {
        const int p4 = ch * 16 + (tid & 15);
        const int q  = tid >> 4;                       // 0..7
        const float4* base = (const float4*)g_partial + (size_t)bb * NCHUNK * 1024 + p4;
        float4 s = make_float4(0.f, 0.f, 0.f, 0.f);
        #pragma unroll
        for (int c = 0; c < 16; ++c) {
            float4 v = __ldcg(base + (size_t)(q * 16 + c) * 1024);
            s.x += v.x; s.y += v.y; s.z += v.z; s.w += v.w;
        }
        s4[tid] = s;
        __syncthreads();
        if (tid < 16) {
            float4 r = s4[tid];
            #pragma unroll
            for (int k = 1; k < 8; ++k) {
                float4 v = s4[tid + k * 16];
                r.x += v.x; r.y += v.y; r.z += v.z; r.w += v.w;
            }
            const float cf = sCoeff;
            r.x *= cf; r.y *= cf; r.z *= cf; r.w *= cf;
            ((float4*)g_K)[bb * 1024 + ch * 16 + tid] = r;
            float ls = r.x + r.y + r.z + r.w;
            #pragma unroll
            for (int o = 8; o; o >>= 1) ls += __shfl_xor_sync(0xFFFFu, ls, o);
            if (tid == 0) g_ssum[bb * NBLK + ch] = ls;
        }
        __syncthreads();
    }
    if (tid == 0) {
        __threadfence();
        unsigned old = atomicAdd(&g_cntC[bb], 1u);
        sIsLast = (old == NBLK - 1) ? 1 : 0;
    }
    __syncthreads();
    if (!sIsLast) return;

    // ================= Finalize (one block per batch) =================
    __threadfence();
    if (tid < 32) {
        float v = __ldcg(&g_ssum[bb * NBLK + tid]) + __ldcg(&g_ssum[bb * NBLK + 32 + tid]);
        #pragma unroll
        for (int o = 16; o; o >>= 1) v += __shfl_xor_sync(~0u, v, o);
        if (tid == 0) sInv = 1.0f / fmaxf(v, 1e-5f);
    }
    __syncthreads();
    const float inv = sInv;
    const float4* kp = (const float4*)g_K + bb * 1024;
    float4* op = (float4*)out + bb * 1024;
    #pragma unroll
    for (int k = 0; k < 8; ++k) {
        float4 v = __ldcg(kp + tid + k * NTHR);
        v.x *= inv; v.y *= inv; v.z *= inv; v.w *= inv;
        op[tid + k * NTHR] = v;
    }
    if (tid == 0) { g_cntA[bb] = 0u; g_cntB[bb] = 0u; g_cntC[bb] = 0u; }
}

extern "C" void kernel_launch(void* const* d_in, const int* in_sizes, int n_in,
                              void* d_out, int out_size)
{
    const float* T = (const float*)d_in[0];
    const float* S = (const float*)d_in[1];
    if (n_in >= 2 && in_sizes[0] == BATCH * NSAMP * 2 &&
        in_sizes[1] == BATCH * NVERT * 2) {
        T = (const float*)d_in[1];
        S = (const float*)d_in[0];
    }
    k_fused<<<BATCH * NBLK, NTHR>>>(T, S, (float*)d_out);
}

// round 8
// speedup vs baseline: 1.3901x; 1.3901x over previous
#include <cuda_runtime.h>
#include <math.h>

#define BATCH 8
#define NVERT 8192
#define NPD 64
#define NSAMP (NPD*NPD)      // 4096
#define CH 32                // chunks (blocks) per batch
#define JCHUNK (NVERT/CH)    // 256 vertices per block
#define NK16 (JCHUNK/16)     // 16 k-steps of 16
#define NTHR 128
#define BSTR 72              // smem row stride (words) for B: conflict-free gather

// ---- device scratch (no allocations allowed) ----
__device__ float4   g_stats[BATCH*CH];
__device__ float    g_partial[BATCH*CH*NSAMP];  // 4 MB
__device__ float    g_K[BATCH*NSAMP];
__device__ float    g_ssum[BATCH*CH];
__device__ unsigned g_cntA[BATCH];
__device__ unsigned g_cntB[BATCH];
__device__ unsigned g_cntC[BATCH];

__device__ __forceinline__ float ex2f(float x) {
    float y; asm("ex2.approx.ftz.f32 %0, %1;" : "=f"(y) : "f"(x)); return y;
}
// pack (ve -> low bf16, vo -> high bf16); also return lo-residual pack
__device__ __forceinline__ void split_pair(float ve, float vo, unsigned& hi, unsigned& lo) {
    asm("cvt.rn.bf16x2.f32 %0, %1, %2;" : "=r"(hi) : "f"(vo), "f"(ve));
    float he = __uint_as_float(hi << 16);
    float ho = __uint_as_float(hi & 0xFFFF0000u);
    float le = ve - he, l_o = vo - ho;
    asm("cvt.rn.bf16x2.f32 %0, %1, %2;" : "=r"(lo) : "f"(l_o), "f"(le));
}
__device__ __forceinline__ void mma_bf16(float* d, const unsigned* a, unsigned b0, unsigned b1) {
    asm("mma.sync.aligned.m16n8k16.row.col.f32.bf16.bf16.f32 "
        "{%0,%1,%2,%3}, {%4,%5,%6,%7}, {%8,%9}, {%0,%1,%2,%3};"
        : "+f"(d[0]), "+f"(d[1]), "+f"(d[2]), "+f"(d[3])
        : "r"(a[0]), "r"(a[1]), "r"(a[2]), "r"(a[3]), "r"(b0), "r"(b1));
}
__device__ __forceinline__ void spin_until(volatile unsigned* p, unsigned v) {
    while (*p < v) { }
}

// ==================== single fused persistent kernel ====================
// grid = 256 blocks (batch = blk>>5, chunk = blk&31), 128 threads (4 warps).
// Phase B: warp w computes D rows [w*16, +16) x 64 cols via mma.sync bf16-split.
__global__ void __launch_bounds__(NTHR) k_fused(const float* __restrict__ T,
                                                const float* __restrict__ S,
                                                float* __restrict__ out)
{
    __shared__ __align__(16) float2 sT[JCHUNK];          // 2 KB
    __shared__ __align__(16) unsigned sBhi[2][8*BSTR];   // 4.5 KB x2
    __shared__ __align__(16) unsigned sBlo[2][8*BSTR];
    __shared__ __align__(16) float4 s4[NTHR];            // 2 KB
    __shared__ float  sG[NPD];
    __shared__ float4 sW[4];
    __shared__ float  sKx, sCoeff, sInv;
    __shared__ int    sIsLast;

    const int tid  = threadIdx.x;
    const int wid  = tid >> 5;
    const int lane = tid & 31;
    const int bb   = blockIdx.x >> 5;
    const int ch   = blockIdx.x & 31;

    // ---- stage T chunk + grid ----
    ((float4*)sT)[tid] = ((const float4*)(T + (bb * NVERT + ch * JCHUNK) * 2))[tid];
    if (tid < NPD) sG[tid] = S[tid * 2 + 1];   // S[0,c,1] = g[c] exactly
    __syncthreads();

    // ================= Phase A: chunk stats + sigma =================
    {
        float2 v0 = sT[tid], v1 = sT[tid + 128];
        float sx = v0.x + v1.x, sy = v0.y + v1.y;
        float sxx = v0.x*v0.x + v1.x*v1.x, syy = v0.y*v0.y + v1.y*v1.y;
        #pragma unroll
        for (int o = 16; o; o >>= 1) {
            sx  += __shfl_xor_sync(~0u, sx,  o);
            sxx += __shfl_xor_sync(~0u, sxx, o);
            sy  += __shfl_xor_sync(~0u, sy,  o);
            syy += __shfl_xor_sync(~0u, syy, o);
        }
        if (lane == 0) sW[wid] = make_float4(sx, sxx, sy, syy);
        __syncthreads();
        if (tid == 0) {
            float4 r = sW[0];
            #pragma unroll
            for (int w = 1; w < 4; ++w) {
                r.x += sW[w].x; r.y += sW[w].y; r.z += sW[w].z; r.w += sW[w].w;
            }
            g_stats[blockIdx.x] = r;
            __threadfence();
            atomicAdd(&g_cntA[bb], 1u);
            spin_until(&g_cntA[bb], CH);
            __threadfence();
        }
        __syncthreads();
    }
    if (tid < 32) {
        float4 st = __ldcg(&g_stats[bb * 32 + tid]);
        float sx = st.x, sxx = st.y, sy = st.z, syy = st.w;
        #pragma unroll
        for (int o = 16; o; o >>= 1) {
            sx  += __shfl_xor_sync(~0u, sx,  o);
            sxx += __shfl_xor_sync(~0u, sxx, o);
            sy  += __shfl_xor_sync(~0u, sy,  o);
            syy += __shfl_xor_sync(~0u, syy, o);
        }
        if (tid == 0) {
            const double n = (double)NVERT;
            double vx = ((double)sxx - (double)sx*(double)sx/n) / (n - 1.0);
            double vy = ((double)syy - (double)sy*(double)sy/n) / (n - 1.0);
            if (vx < 0.0) vx = 0.0;
            if (vy < 0.0) vy = 0.0;
            double sigma = 0.5 * (sqrt(vx) + sqrt(vy));
            const double bd = 1.0 / 63.0;
            if (sigma < bd) sigma = bd;
            const double p  = exp2(13.0 / 3.0);   // CN=-p/2, CF=p/(2pi)
            const double s2 = sigma * sigma;
            sKx    = (float)((-0.5 * p) / s2 * 1.4426950408889634);
            sCoeff = (float)((p / (2.0 * M_PI)) / s2 / (double)NVERT);
        }
    }
    __syncthreads();
    const float kx = sKx;

    // ================= Phase B: mma.sync bf16-split GEMM =================
    // D[a,n] (64x64) += Ex[a,j] * Ey[n,j]; A frags in registers, B via smem.
    float dacc[8][4];
    #pragma unroll
    for (int nt = 0; nt < 8; ++nt)
        #pragma unroll
        for (int i = 0; i < 4; ++i) dacc[nt][i] = 0.f;

    const int g = lane >> 2;          // 0..7
    const int q = lane & 3;           // 0..3
    const int r0 = wid * 16 + g;      // A row (low 8)
    const int r1 = r0 + 8;            // A row (high 8)
    const float ga0 = sG[r0], ga1 = sG[r1];
    // B fill slots: 4 per thread, slot = tid + i*128; n = slot&63, kpair = slot>>6
    const int fn  = tid & 63;
    const float gn = sG[fn];

    // Prologue: fill B for step 0 into buf 0
    #pragma unroll
    for (int i = 0; i < 4; ++i) {
        const int kp = (tid + i * 128) >> 6;     // 0..7
        const float2 t0 = sT[kp * 2];
        const float2 t1 = sT[kp * 2 + 1];
        float d0 = gn - t0.y, d1 = gn - t1.y;
        float v0 = ex2f(kx * (d0 * d0)), v1 = ex2f(kx * (d1 * d1));
        unsigned hi, lo; split_pair(v0, v1, hi, lo);
        sBhi[0][kp * BSTR + fn] = hi;
        sBlo[0][kp * BSTR + fn] = lo;
    }
    __syncthreads();

    for (int s = 0; s < NK16; ++s) {
        const int cur = s & 1;
        // ---- fill B(s+1) into !cur ----
        if (s + 1 < NK16) {
            const int j16 = (s + 1) * 16;
            #pragma unroll
            for (int i = 0; i < 4; ++i) {
                const int kp = (tid + i * 128) >> 6;
                const float2 t0 = sT[j16 + kp * 2];
                const float2 t1 = sT[j16 + kp * 2 + 1];
                float d0 = gn - t0.y, d1 = gn - t1.y;
                float v0 = ex2f(kx * (d0 * d0)), v1 = ex2f(kx * (d1 * d1));
                unsigned hi, lo; split_pair(v0, v1, hi, lo);
                sBhi[cur ^ 1][kp * BSTR + fn] = hi;
                sBlo[cur ^ 1][kp * BSTR + fn] = lo;
            }
        }
        // ---- A fragments for step s (registers, no smem) ----
        const int j16 = s * 16;
        const float tx0 = sT[j16 + 2*q    ].x;
        const float tx1 = sT[j16 + 2*q + 1].x;
        const float tx2 = sT[j16 + 2*q + 8].x;
        const float tx3 = sT[j16 + 2*q + 9].x;
        float e;
        e = ga0 - tx0; const float v00 = ex2f(kx * (e*e));
        e = ga0 - tx1; const float v01 = ex2f(kx * (e*e));
        e = ga1 - tx0; const float v10 = ex2f(kx * (e*e));
        e = ga1 - tx1; const float v11 = ex2f(kx * (e*e));
        e = ga0 - tx2; const float v02 = ex2f(kx * (e*e));
        e = ga0 - tx3; const float v03 = ex2f(kx * (e*e));
        e = ga1 - tx2; const float v12 = ex2f(kx * (e*e));
        e = ga1 - tx3; const float v13 = ex2f(kx * (e*e));
        unsigned ah[4], al[4];
        split_pair(v00, v01, ah[0], al[0]);
        split_pair(v10, v11, ah[1], al[1]);
        split_pair(v02, v03, ah[2], al[2]);
        split_pair(v12, v13, ah[3], al[3]);
        // ---- GEMM: 8 n-tiles x 3 passes ----
        const unsigned* bh = &sBhi[cur][0];
        const unsigned* bl = &sBlo[cur][0];
        const int bi0 = q * BSTR + g;            // kpair q   (b0)
        const int bi1 = (q + 4) * BSTR + g;      // kpair q+4 (b1)
        #pragma unroll
        for (int nt = 0; nt < 8; ++nt) {
            const unsigned bh0 = bh[bi0 + nt * 8];
            const unsigned bh1 = bh[bi1 + nt * 8];
            const unsigned bl0 = bl[bi0 + nt * 8];
            const unsigned bl1 = bl[bi1 + nt * 8];
            mma_bf16(dacc[nt], ah, bh0, bh1);
            mma_bf16(dacc[nt], ah, bl0, bl1);
            mma_bf16(dacc[nt], al, bh0, bh1);
        }
        __syncthreads();
    }

    // write this block's 64x64 partial (rows r0/r1, cols nt*8 + 2q,+1)
    {
        float* outp = g_partial + (size_t)blockIdx.x * NSAMP;
        #pragma unroll
        for (int nt = 0; nt < 8; ++nt) {
            const int n0 = nt * 8 + 2 * q;
            *(float2*)(outp + r0 * NPD + n0) = make_float2(dacc[nt][0], dacc[nt][1]);
            *(float2*)(outp + r1 * NPD + n0) = make_float2(dacc[nt][2], dacc[nt][3]);
        }
    }
    __threadfence();
    __syncthreads();
    if (tid == 0) {
        atomicAdd(&g_cntB[bb], 1u);
        spin_until(&g_cntB[bb], CH);
        __threadfence();
    }
    __syncthreads();

    // ================= Phase C: cooperative reduce + segment sums =================
    {
        const int p4 = ch * 32 + lane;
        const int qq = wid;                            // 0..3
        const float4* base = (const float4*)g_partial + (size_t)bb * 32 * 1024 + p4;
        float4 s = make_float4(0.f, 0.f, 0.f, 0.f);
        #pragma unroll
        for (int c = 0; c < 8; ++c) {
            float4 v = __ldcg(base + (size_t)(qq * 8 + c) * 1024);
            s.x += v.x; s.y += v.y; s.z += v.z; s.w += v.w;
        }
        s4[tid] = s;
        __syncthreads();
        if (tid < 32) {
            float4 r = s4[tid];
            #pragma unroll
            for (int k = 1; k < 4; ++k) {
                float4 v = s4[tid + k * 32];
                r.x += v.x; r.y += v.y; r.z += v.z; r.w += v.w;
            }
            const float cf = sCoeff;
            r.x *= cf; r.y *= cf; r.z *= cf; r.w *= cf;
            ((float4*)g_K)[bb * 1024 + ch * 32 + tid] = r;
            float ls = r.x + r.y + r.z + r.w;
            #pragma unroll
            for (int o = 16; o; o >>= 1) ls += __shfl_xor_sync(~0u, ls, o);
            if (tid == 0) g_ssum[bb * 32 + ch] = ls;
        }
        __syncthreads();
    }
    if (tid == 0) {
        __threadfence();
        unsigned old = atomicAdd(&g_cntC[bb], 1u);
        sIsLast = (old == CH - 1) ? 1 : 0;
    }
    __syncthreads();
    if (!sIsLast) return;

    // ================= Finalize (one block per batch) =================
    __threadfence();
    if (tid < 32) {
        float v = __ldcg(&g_ssum[bb * 32 + tid]);
        #pragma unroll
        for (int o = 16; o; o >>= 1) v += __shfl_xor_sync(~0u, v, o);
        if (tid == 0) sInv = 1.0f / fmaxf(v, 1e-5f);
    }
    __syncthreads();
    const float inv = sInv;
    const float4* kp = (const float4*)g_K + bb * 1024;
    float4* op = (float4*)out + bb * 1024;
    #pragma unroll
    for (int k = 0; k < 8; ++k) {
        float4 v = __ldcg(kp + tid + k * NTHR);
        v.x *= inv; v.y *= inv; v.z *= inv; v.w *= inv;
        op[tid + k * NTHR] = v;
    }
    if (tid == 0) { g_cntA[bb] = 0u; g_cntB[bb] = 0u; g_cntC[bb] = 0u; }
}

extern "C" void kernel_launch(void* const* d_in, const int* in_sizes, int n_in,
                              void* d_out, int out_size)
{
    const float* T = (const float*)d_in[0];
    const float* S = (const float*)d_in[1];
    if (n_in >= 2 && in_sizes[0] == BATCH * NSAMP * 2 &&
        in_sizes[1] == BATCH * NVERT * 2) {
        T = (const float*)d_in[1];
        S = (const float*)d_in[0];
    }
    k_fused<<<BATCH * CH, NTHR>>>(T, S, (float*)d_out);
}

// round 9
// speedup vs baseline: 1.4519x; 1.0444x over previous
#include <cuda_runtime.h>
#include <math.h>

#define BATCH 8
#define NVERT 8192
#define NPD 64
#define NSAMP (NPD*NPD)      // 4096
#define CH 64                // chunks (blocks) per batch
#define JCHUNK (NVERT/CH)    // 128 vertices per block
#define NK16 (JCHUNK/16)     // 8 k-steps of 16
#define NTHR 128
#define BSTR 72              // smem row stride (words) for B: conflict-free gather

// ---- device scratch (no allocations allowed) ----
__device__ float4   g_stats[BATCH*CH];
__device__ float    g_partial[BATCH*CH*NSAMP];  // 8 MB
__device__ float    g_K[BATCH*NSAMP];
__device__ float    g_ssum[BATCH*CH];
__device__ unsigned g_cntA[BATCH];
__device__ unsigned g_cntB[BATCH];
__device__ unsigned g_cntC[BATCH];

__device__ __forceinline__ float ex2f(float x) {
    float y; asm("ex2.approx.ftz.f32 %0, %1;" : "=f"(y) : "f"(x)); return y;
}
// pack (ve -> low bf16, vo -> high bf16); also return lo-residual pack
__device__ __forceinline__ void split_pair(float ve, float vo, unsigned& hi, unsigned& lo) {
    asm("cvt.rn.bf16x2.f32 %0, %1, %2;" : "=r"(hi) : "f"(vo), "f"(ve));
    float he = __uint_as_float(hi << 16);
    float ho = __uint_as_float(hi & 0xFFFF0000u);
    float le = ve - he, l_o = vo - ho;
    asm("cvt.rn.bf16x2.f32 %0, %1, %2;" : "=r"(lo) : "f"(l_o), "f"(le));
}
__device__ __forceinline__ void mma_bf16(float* d, const unsigned* a, unsigned b0, unsigned b1) {
    asm("mma.sync.aligned.m16n8k16.row.col.f32.bf16.bf16.f32 "
        "{%0,%1,%2,%3}, {%4,%5,%6,%7}, {%8,%9}, {%0,%1,%2,%3};"
        : "+f"(d[0]), "+f"(d[1]), "+f"(d[2]), "+f"(d[3])
        : "r"(a[0]), "r"(a[1]), "r"(a[2]), "r"(a[3]), "r"(b0), "r"(b1));
}
__device__ __forceinline__ void spin_until(volatile unsigned* p, unsigned v) {
    while (*p < v) { }
}

// ==================== single fused persistent kernel ====================
// grid = 512 blocks (batch = blk>>6, chunk = blk&63), 128 threads (4 warps).
// ~4 blocks/SM co-resident -> independent blocks hide each other's latency.
__global__ void __launch_bounds__(NTHR, 4) k_fused(const float* __restrict__ T,
                                                   const float* __restrict__ S,
                                                   float* __restrict__ out)
{
    __shared__ __align__(16) float2 sT[JCHUNK];          // 1 KB
    __shared__ __align__(16) unsigned sBhi[2][8*BSTR];   // 2.25 KB x2
    __shared__ __align__(16) unsigned sBlo[2][8*BSTR];
    __shared__ __align__(16) float4 s4[NTHR];            // 2 KB
    __shared__ float  sG[NPD];
    __shared__ float4 sW[4];
    __shared__ float  sKx, sCoeff, sInv;
    __shared__ int    sIsLast;

    const int tid  = threadIdx.x;
    const int wid  = tid >> 5;
    const int lane = tid & 31;
    const int bb   = blockIdx.x >> 6;
    const int ch   = blockIdx.x & 63;

    // ---- stage T chunk + grid ----
    ((float2*)sT)[tid] = ((const float2*)(T + (bb * NVERT + ch * JCHUNK) * 2))[tid];
    if (tid < NPD) sG[tid] = S[tid * 2 + 1];   // S[0,c,1] = g[c] exactly
    __syncthreads();

    // ================= Phase A: chunk stats + sigma =================
    {
        float2 v0 = sT[tid];                   // one vertex per thread
        float sx = v0.x, sy = v0.y;
        float sxx = v0.x * v0.x, syy = v0.y * v0.y;
        #pragma unroll
        for (int o = 16; o; o >>= 1) {
            sx  += __shfl_xor_sync(~0u, sx,  o);
            sxx += __shfl_xor_sync(~0u, sxx, o);
            sy  += __shfl_xor_sync(~0u, sy,  o);
            syy += __shfl_xor_sync(~0u, syy, o);
        }
        if (lane == 0) sW[wid] = make_float4(sx, sxx, sy, syy);
        __syncthreads();
        if (tid == 0) {
            float4 r = sW[0];
            #pragma unroll
            for (int w = 1; w < 4; ++w) {
                r.x += sW[w].x; r.y += sW[w].y; r.z += sW[w].z; r.w += sW[w].w;
            }
            g_stats[blockIdx.x] = r;
            __threadfence();
            atomicAdd(&g_cntA[bb], 1u);
            spin_until(&g_cntA[bb], CH);
            __threadfence();
        }
        __syncthreads();
    }
    if (tid < 32) {
        float4 sa = __ldcg(&g_stats[bb * CH + tid]);
        float4 sb = __ldcg(&g_stats[bb * CH + 32 + tid]);
        float sx = sa.x + sb.x, sxx = sa.y + sb.y;
        float sy = sa.z + sb.z, syy = sa.w + sb.w;
        #pragma unroll
        for (int o = 16; o; o >>= 1) {
            sx  += __shfl_xor_sync(~0u, sx,  o);
            sxx += __shfl_xor_sync(~0u, sxx, o);
            sy  += __shfl_xor_sync(~0u, sy,  o);
            syy += __shfl_xor_sync(~0u, syy, o);
        }
        if (tid == 0) {
            const double n = (double)NVERT;
            double vx = ((double)sxx - (double)sx*(double)sx/n) / (n - 1.0);
            double vy = ((double)syy - (double)sy*(double)sy/n) / (n - 1.0);
            if (vx < 0.0) vx = 0.0;
            if (vy < 0.0) vy = 0.0;
            double sigma = 0.5 * (sqrt(vx) + sqrt(vy));
            const double bd = 1.0 / 63.0;
            if (sigma < bd) sigma = bd;
            const double p  = exp2(13.0 / 3.0);   // CN=-p/2, CF=p/(2pi)
            const double s2 = sigma * sigma;
            sKx    = (float)((-0.5 * p) / s2 * 1.4426950408889634);
            sCoeff = (float)((p / (2.0 * M_PI)) / s2 / (double)NVERT);
        }
    }
    __syncthreads();
    const float kx = sKx;

    // ================= Phase B: mma.sync bf16-split GEMM =================
    // D[a,n] (64x64) += Ex[a,j] * Ey[n,j]; A frags in registers, B via smem.
    float dacc[8][4];
    #pragma unroll
    for (int nt = 0; nt < 8; ++nt)
        #pragma unroll
        for (int i = 0; i < 4; ++i) dacc[nt][i] = 0.f;

    const int g = lane >> 2;          // 0..7
    const int q = lane & 3;           // 0..3
    const int r0 = wid * 16 + g;      // A row (low 8)
    const int r1 = r0 + 8;            // A row (high 8)
    const float ga0 = sG[r0], ga1 = sG[r1];
    // B fill slots: 4 per thread, slot = tid + i*128; n = slot&63, kpair = slot>>6
    const int fn  = tid & 63;
    const float gn = sG[fn];

    // Prologue: fill B for step 0 into buf 0
    #pragma unroll
    for (int i = 0; i < 4; ++i) {
        const int kp = (tid + i * 128) >> 6;     // 0..7
        const float2 t0 = sT[kp * 2];
        const float2 t1 = sT[kp * 2 + 1];
        float d0 = gn - t0.y, d1 = gn - t1.y;
        float v0 = ex2f(kx * (d0 * d0)), v1 = ex2f(kx * (d1 * d1));
        unsigned hi, lo; split_pair(v0, v1, hi, lo);
        sBhi[0][kp * BSTR + fn] = hi;
        sBlo[0][kp * BSTR + fn] = lo;
    }
    __syncthreads();

    for (int s = 0; s < NK16; ++s) {
        const int cur = s & 1;
        // ---- fill B(s+1) into !cur ----
        if (s + 1 < NK16) {
            const int j16 = (s + 1) * 16;
            #pragma unroll
            for (int i = 0; i < 4; ++i) {
                const int kp = (tid + i * 128) >> 6;
                const float2 t0 = sT[j16 + kp * 2];
                const float2 t1 = sT[j16 + kp * 2 + 1];
                float d0 = gn - t0.y, d1 = gn - t1.y;
                float v0 = ex2f(kx * (d0 * d0)), v1 = ex2f(kx * (d1 * d1));
                unsigned hi, lo; split_pair(v0, v1, hi, lo);
                sBhi[cur ^ 1][kp * BSTR + fn] = hi;
                sBlo[cur ^ 1][kp * BSTR + fn] = lo;
            }
        }
        // ---- A fragments for step s (registers, no smem) ----
        const int j16 = s * 16;
        const float tx0 = sT[j16 + 2*q    ].x;
        const float tx1 = sT[j16 + 2*q + 1].x;
        const float tx2 = sT[j16 + 2*q + 8].x;
        const float tx3 = sT[j16 + 2*q + 9].x;
        float e;
        e = ga0 - tx0; const float v00 = ex2f(kx * (e*e));
        e = ga0 - tx1; const float v01 = ex2f(kx * (e*e));
        e = ga1 - tx0; const float v10 = ex2f(kx * (e*e));
        e = ga1 - tx1; const float v11 = ex2f(kx * (e*e));
        e = ga0 - tx2; const float v02 = ex2f(kx * (e*e));
        e = ga0 - tx3; const float v03 = ex2f(kx * (e*e));
        e = ga1 - tx2; const float v12 = ex2f(kx * (e*e));
        e = ga1 - tx3; const float v13 = ex2f(kx * (e*e));
        unsigned ah[4], al[4];
        split_pair(v00, v01, ah[0], al[0]);
        split_pair(v10, v11, ah[1], al[1]);
        split_pair(v02, v03, ah[2], al[2]);
        split_pair(v12, v13, ah[3], al[3]);
        // ---- GEMM: 8 n-tiles x 3 passes ----
        const unsigned* bh = &sBhi[cur][0];
        const unsigned* bl = &sBlo[cur][0];
        const int bi0 = q * BSTR + g;            // kpair q   (b0)
        const int bi1 = (q + 4) * BSTR + g;      // kpair q+4 (b1)
        #pragma unroll
        for (int nt = 0; nt < 8; ++nt) {
            const unsigned bh0 = bh[bi0 + nt * 8];
            const unsigned bh1 = bh[bi1 + nt * 8];
            const unsigned bl0 = bl[bi0 + nt * 8];
            const unsigned bl1 = bl[bi1 + nt * 8];
            mma_bf16(dacc[nt], ah, bh0, bh1);
            mma_bf16(dacc[nt], ah, bl0, bl1);
            mma_bf16(dacc[nt], al, bh0, bh1);
        }
        __syncthreads();
    }

    // write this block's 64x64 partial (rows r0/r1, cols nt*8 + 2q,+1)
    {
        float* outp = g_partial + (size_t)blockIdx.x * NSAMP;
        #pragma unroll
        for (int nt = 0; nt < 8; ++nt) {
            const int n0 = nt * 8 + 2 * q;
            *(float2*)(outp + r0 * NPD + n0) = make_float2(dacc[nt][0], dacc[nt][1]);
            *(float2*)(outp + r1 * NPD + n0) = make_float2(dacc[nt][2], dacc[nt][3]);
        }
    }
    __threadfence();
    __syncthreads();
    if (tid == 0) {
        atomicAdd(&g_cntB[bb], 1u);
        spin_until(&g_cntB[bb], CH);
        __threadfence();
    }
    __syncthreads();

    // ================= Phase C: cooperative reduce + segment sums =================
    // Block (bb,ch) reduces image float4 positions [ch*16, ch*16+16) over 64 chunks.
    {
        const int p4 = ch * 16 + (tid & 15);
        const int qq = tid >> 4;                       // 0..7
        const float4* base = (const float4*)g_partial + (size_t)bb * CH * 1024 + p4;
        float4 s = make_float4(0.f, 0.f, 0.f, 0.f);
        #pragma unroll
        for (int c = 0; c < 8; ++c) {
            float4 v = __ldcg(base + (size_t)(qq * 8 + c) * 1024);
            s.x += v.x; s.y += v.y; s.z += v.z; s.w += v.w;
        }
        s4[tid] = s;
        __syncthreads();
        if (tid < 16) {
            float4 r = s4[tid];
            #pragma unroll
            for (int k = 1; k < 8; ++k) {
                float4 v = s4[tid + k * 16];
                r.x += v.x; r.y += v.y; r.z += v.z; r.w += v.w;
            }
            const float cf = sCoeff;
            r.x *= cf; r.y *= cf; r.z *= cf; r.w *= cf;
            ((float4*)g_K)[bb * 1024 + ch * 16 + tid] = r;
            float ls = r.x + r.y + r.z + r.w;
            #pragma unroll
            for (int o = 8; o; o >>= 1) ls += __shfl_xor_sync(0xFFFFu, ls, o);
            if (tid == 0) g_ssum[bb * CH + ch] = ls;
        }
        __syncthreads();
    }
    if (tid == 0) {
        __threadfence();
        unsigned old = atomicAdd(&g_cntC[bb], 1u);
        sIsLast = (old == CH - 1) ? 1 : 0;
    }
    __syncthreads();
    if (!sIsLast) return;

    // ================= Finalize (one block per batch) =================
    __threadfence();
    if (tid < 32) {
        float v = __ldcg(&g_ssum[bb * CH + tid]) + __ldcg(&g_ssum[bb * CH + 32 + tid]);
        #pragma unroll
        for (int o = 16; o; o >>= 1) v += __shfl_xor_sync(~0u, v, o);
        if (tid == 0) sInv = 1.0f / fmaxf(v, 1e-5f);
    }
    __syncthreads();
    const float inv = sInv;
    const float4* kp = (const float4*)g_K + bb * 1024;
    float4* op = (float4*)out + bb * 1024;
    #pragma unroll
    for (int k = 0; k < 8; ++k) {
        float4 v = __ldcg(kp + tid + k * NTHR);
        v.x *= inv; v.y *= inv; v.z *= inv; v.w *= inv;
        op[tid + k * NTHR] = v;
    }
    if (tid == 0) { g_cntA[bb] = 0u; g_cntB[bb] = 0u; g_cntC[bb] = 0u; }
}

extern "C" void kernel_launch(void* const* d_in, const int* in_sizes, int n_in,
                              void* d_out, int out_size)
{
    const float* T = (const float*)d_in[0];
    const float* S = (const float*)d_in[1];
    if (n_in >= 2 && in_sizes[0] == BATCH * NSAMP * 2 &&
        in_sizes[1] == BATCH * NVERT * 2) {
        T = (const float*)d_in[1];
        S = (const float*)d_in[0];
    }
    k_fused<<<BATCH * CH, NTHR>>>(T, S, (float*)d_out);
}